// round 13
// baseline (speedup 1.0000x reference)
#include <cuda_runtime.h>

#define D      256
#define NDAY   7
#define NT     288
#define NC     (NDAY * NT)        // 2016 distinct (day, tod) combos
#define ROWS   (64 * 2048)        // B * S = 131072
#define MTILE  16                 // combos per m-block
#define NMB    (NC / MTILE)       // 126 m-blocks
#define KSPLIT 8                  // k-eighths
#define KQ     (D / KSPLIT)       // 32 k-values per build task
#define MPT    (MTILE / 2)        // 8 combos per thread (2 column-halves)
#define CAP    256                // bucket capacity (mean 65, max ~105)

#define NT_SCAT   (ROWS / 256)    // 512 scatter tasks
#define NT_BUILD  (NMB * KSPLIT)  // 1008 build tasks
#define NT_WRITE  NC              // 2016 write tasks
#define HEAD_B    128             // build head-start (16 mbs)
#define TRIPLES   ((NT_BUILD - HEAD_B) * 3)   // 2640: [1 build : 2 writes]
#define NTASKS    (NT_SCAT + HEAD_B + TRIPLES + (NT_WRITE - 2 * (NT_BUILD - HEAD_B)))
// = 512 + 128 + 2640 + 256 = 3536

#define GRID 592                  // 4 CTAs/SM x 148 SMs: provably one wave

// K-split partial sums of the combo table. 8 x 2 MB. b2 folded into part 0.
__device__ float    g_part[KSPLIT][NC * D];
// Per-combo row buckets (self-resetting).
__device__ int      g_cnt[NC];
__device__ int      g_rowlist[NC * CAP];
// Pipeline state (all self-resetting; zero at module load).
__device__ unsigned g_task;               // work-queue head
__device__ unsigned g_exited;             // CTAs that left the loop
__device__ unsigned g_scat_done;          // target NT_SCAT
__device__ unsigned g_done_mb[NMB];       // target KSPLIT
__device__ unsigned g_wpass_mb[NMB];      // MTILE writes per mb
__device__ unsigned g_wpass_total;        // NT_WRITE writes overall

// -------------------------------------------------------------------------
// Single persistent one-wave kernel with a dynamic work queue.
// Queue order: [512 scatter][128 builds (mbs 0..15)][triples: 1 build + 2
// writes — builds lead their consumer writes by ~364 positions][256 tail
// writes]. Writers wait on flags; their producers were pulled ~0.6 waves
// earlier by co-resident CTAs, so spins are short and cannot starve builds
// (the failure mode of R10/R11/R12).
// -------------------------------------------------------------------------
__global__ void __launch_bounds__(256, 4) fused_queue(
    const float* __restrict__ W1, const float* __restrict__ b1,
    const float* __restrict__ W2, const float* __restrict__ b2,
    const void* __restrict__ TEp, float* __restrict__ out)
{
    const int tid  = threadIdx.x;
    const int lane = tid & 31;
    const int warp = tid >> 5;

    __shared__ __align__(16) float h_sh[MTILE][KQ];   // 2 KB (build)
    __shared__ __align__(16) float row_sh[D];         // 1 KB (write)
    __shared__ unsigned s_task;

    for (;;) {
        if (tid == 0) s_task = atomicAdd(&g_task, 1u);
        __syncthreads();
        const unsigned task = s_task;
        __syncthreads();
        if (task >= (unsigned)NTASKS) break;

        // ---------------- decode queue position -> work item ----------------
        int kind;        // 0 = scatter, 1 = build, 2 = write
        int p0;          // scatter idx / build idx / combo idx
        if (task < NT_SCAT) {
            kind = 0; p0 = (int)task;
        } else if (task < NT_SCAT + HEAD_B) {
            kind = 1; p0 = (int)task - NT_SCAT;
        } else if (task < (unsigned)(NT_SCAT + HEAD_B + TRIPLES)) {
            int k = (int)task - (NT_SCAT + HEAD_B);
            int q = k / 3, r = k - q * 3;
            if (r == 0) { kind = 1; p0 = HEAD_B + q; }
            else        { kind = 2; p0 = 2 * q + (r - 1); }
        } else {
            kind = 2; p0 = 2 * (NT_BUILD - HEAD_B) + ((int)task - (NT_SCAT + HEAD_B + TRIPLES));
        }

        if (kind == 0) {
            // ============================ scatter ============================
            // Per-warp TE dtype detect: values 0..287 -> int64 layout has
            // all-zero high 32-bit words; int32 layout has random indices.
            const unsigned long long* TE64 = (const unsigned long long*)TEp;
            unsigned long long hv = (TE64[lane] >> 32) | (TE64[lane + 32] >> 32);
            bool is64 = (__ballot_sync(0xffffffffu, hv != 0ULL) == 0u);

            const int row = p0 * 256 + tid;
            int t0, t1;
            if (is64) {
                longlong2 te = reinterpret_cast<const longlong2*>(TEp)[row];
                t0 = (int)te.x; t1 = (int)te.y;
            } else {
                int2 te = reinterpret_cast<const int2*>(TEp)[row];
                t0 = te.x; t1 = te.y;
            }
            int day = t0 % NDAY; day += (day >> 31) & NDAY;
            int tod = t1 % NT;   tod += (tod >> 31) & NT;
            int c   = day * NT + tod;
            int slot = atomicAdd(&g_cnt[c], 1);
            if (slot < CAP) g_rowlist[c * CAP + slot] = row;

            __threadfence();
            __syncthreads();
            if (tid == 0) atomicAdd(&g_scat_done, 1u);
        } else if (kind == 1) {
            // ============================= build =============================
            const int mb = p0 >> 3;
            const int ks = p0 & 7;
            const int c0 = mb * MTILE;
            const int k0 = ks * KQ;

            #pragma unroll
            for (int it = 0; it < (MTILE * KQ) / 256; it++) {
                int idx = it * 256 + tid;
                int m   = idx >> 5;            // /KQ
                int kk  = idx & (KQ - 1);
                int c   = c0 + m;
                int day = c / NT;
                int tod = c - day * NT;
                int k   = k0 + kk;
                float v = W1[day * D + k] + W1[(NDAY + tod) * D + k] + b1[k];
                h_sh[m][kk] = fmaxf(v, 0.0f);
            }
            __syncthreads();

            const int e    = tid & 127;
            const int half = tid >> 7;
            const int m0   = half * MPT;

            float acc0[MPT], acc1[MPT];
            const float i0 = (ks == 0) ? b2[e]       : 0.0f;
            const float i1 = (ks == 0) ? b2[e + 128] : 0.0f;
            #pragma unroll
            for (int m = 0; m < MPT; m++) { acc0[m] = i0; acc1[m] = i1; }

            #pragma unroll
            for (int kk = 0; kk < KQ; kk += 4) {
                const float* w = W2 + (size_t)(k0 + kk) * D + e;
                float wa0 = w[0 * D],       wa1 = w[1 * D];
                float wa2 = w[2 * D],       wa3 = w[3 * D];
                float wb0 = w[0 * D + 128], wb1 = w[1 * D + 128];
                float wb2 = w[2 * D + 128], wb3 = w[3 * D + 128];
                #pragma unroll
                for (int m = 0; m < MPT; m++) {
                    float4 h4 = *reinterpret_cast<const float4*>(&h_sh[m0 + m][kk]);
                    acc0[m] = fmaf(h4.x, wa0, acc0[m]);
                    acc0[m] = fmaf(h4.y, wa1, acc0[m]);
                    acc0[m] = fmaf(h4.z, wa2, acc0[m]);
                    acc0[m] = fmaf(h4.w, wa3, acc0[m]);
                    acc1[m] = fmaf(h4.x, wb0, acc1[m]);
                    acc1[m] = fmaf(h4.y, wb1, acc1[m]);
                    acc1[m] = fmaf(h4.z, wb2, acc1[m]);
                    acc1[m] = fmaf(h4.w, wb3, acc1[m]);
                }
            }

            float* __restrict__ part = g_part[ks];
            #pragma unroll
            for (int m = 0; m < MPT; m++) {
                part[(size_t)(c0 + m0 + m) * D + e]       = acc0[m];
                part[(size_t)(c0 + m0 + m) * D + e + 128] = acc1[m];
            }

            __threadfence();
            __syncthreads();
            if (tid == 0) atomicAdd(&g_done_mb[mb], 1u);
        } else {
            // ============================= write =============================
            const int c  = p0;
            const int mb = c / MTILE;

            if (tid == 0) {
                while (atomicAdd(&g_scat_done, 0u) < (unsigned)NT_SCAT) __nanosleep(64);
                while (atomicAdd(&g_done_mb[mb], 0u) < (unsigned)KSPLIT) __nanosleep(64);
                __threadfence();
            }
            __syncthreads();

            if (tid < 64) {
                const size_t base = (size_t)c * (D / 4) + tid;
                float4 s = reinterpret_cast<const float4*>(g_part[0])[base];
                #pragma unroll
                for (int p = 1; p < KSPLIT; p++) {
                    float4 v = reinterpret_cast<const float4*>(g_part[p])[base];
                    s.x += v.x; s.y += v.y; s.z += v.z; s.w += v.w;
                }
                reinterpret_cast<float4*>(row_sh)[tid] = s;
            }
            __syncthreads();

            float4 v0 = reinterpret_cast<const float4*>(row_sh)[lane];
            float4 v1 = reinterpret_cast<const float4*>(row_sh)[lane + 32];

            int cnt = g_cnt[c];
            if (cnt > CAP) cnt = CAP;
            const int* __restrict__ list = g_rowlist + c * CAP;

            for (int i = warp; i < cnt; i += 8) {
                int rr = __ldg(&list[i]);
                float4* __restrict__ dst = reinterpret_cast<float4*>(out + (size_t)rr * D);
                __stcs(dst + lane,      v0);
                __stcs(dst + lane + 32, v1);
            }

            // Self-reset bucket/flag state for the next graph replay.
            __syncthreads();
            if (tid == 0) {
                g_cnt[c] = 0;
                unsigned p = atomicAdd(&g_wpass_mb[mb], 1u);
                if (p == (unsigned)(MTILE - 1)) {
                    g_done_mb[mb]  = 0u;
                    g_wpass_mb[mb] = 0u;
                }
                unsigned q = atomicAdd(&g_wpass_total, 1u);
                if (q == (unsigned)(NT_WRITE - 1)) {
                    g_scat_done   = 0u;
                    g_wpass_total = 0u;
                }
            }
        }
        __syncthreads();   // shared-memory reuse guard between tasks
    }

    // Exit: the LAST CTA to leave resets the queue head for the next replay.
    // No other CTA can pull after it (they have all exited), so this cannot
    // race with a pull.
    __syncthreads();
    if (tid == 0) {
        unsigned e = atomicAdd(&g_exited, 1u);
        if (e == (unsigned)(GRID - 1)) {
            g_task   = 0u;
            g_exited = 0u;
        }
    }
}

// -------------------------------------------------------------------------
// Launch. Inputs resolved by element count:
//   TE = d_in[0]; W1: 295*256 = 75520; W2: 256*256 = 65536; b1/b2: 256 each.
// -------------------------------------------------------------------------
extern "C" void kernel_launch(void* const* d_in, const int* in_sizes, int n_in,
                              void* d_out, int out_size)
{
    const void* TE = d_in[0];
    const float* W1 = nullptr;
    const float* b1 = nullptr;
    const float* W2 = nullptr;
    const float* b2 = nullptr;

    for (int j = 1; j < n_in; j++) {
        int sz = in_sizes[j];
        if (sz == (NDAY + NT) * D) {
            W1 = (const float*)d_in[j];
        } else if (sz == D * D) {
            W2 = (const float*)d_in[j];
        } else if (sz == D) {
            if (!b1) b1 = (const float*)d_in[j];
            else     b2 = (const float*)d_in[j];
        }
    }
    if (!W1 || !b1 || !W2 || !b2) return;

    fused_queue<<<GRID, 256>>>(W1, b1, W2, b2, TE, (float*)d_out);
}

// round 14
// speedup vs baseline: 1.2540x; 1.2540x over previous
#include <cuda_runtime.h>

#define D      256
#define NDAY   7
#define NT     288
#define NC     (NDAY * NT)        // 2016 distinct (day, tod) combos
#define ROWS   (64 * 2048)        // B * S = 131072
#define MTILE  16                 // combos per m-block
#define NMB    (NC / MTILE)       // 126 m-blocks
#define KSPLIT 8                  // k-eighths
#define KQ     (D / KSPLIT)       // 32 k-values per build block
#define MPT    (MTILE / 2)        // 8 combos per thread (2 column-halves)
#define CAP    256                // bucket capacity (mean 65, max ~105)

#define NBLK_BUILD (NMB * KSPLIT) // 1008
#define NBLK_SCAT  (ROWS / 256)   // 512 scatter blocks fused into same grid

// K-split partial sums of the combo table. 8 x 2 MB. b2 folded into part 0.
__device__ float g_part[KSPLIT][NC * D];
// Per-combo row buckets. Zero at module load; write_out re-zeroes after each
// consumption -> zero at every kernel_launch entry (graph-replay safe).
__device__ int   g_cnt[NC];
__device__ int   g_rowlist[NC * CAP];

// -------------------------------------------------------------------------
// Kernel 1 (fused): blocks [0,1008): partial GEMM; blocks [1008,1520):
// scatter rows into per-combo buckets.
// Build: partial[ks][c][e] = sum_{k in eighth ks} relu_h[c][k] * W2[k][e]
//        (+ b2[e] folded into eighth 0)
// Thread: e = tid & 127 -> columns (e, e+128); half = tid>>7 -> 8 combos.
// -------------------------------------------------------------------------
__global__ void __launch_bounds__(256) build_and_scatter(
    const float* __restrict__ W1, const float* __restrict__ b1,
    const float* __restrict__ W2, const float* __restrict__ b2,
    const void* __restrict__ TEp)
{
    const int bx  = blockIdx.x;
    const int tid = threadIdx.x;

    if (bx >= NBLK_BUILD) {
        // ---- scatter block ----
        // Per-warp TE dtype detect: values 0..287 -> int64 layout has
        // all-zero high 32-bit words; int32 layout has random indices.
        const int lane = tid & 31;
        const unsigned long long* TE64 = (const unsigned long long*)TEp;
        unsigned long long hv = (TE64[lane] >> 32) | (TE64[lane + 32] >> 32);
        bool is64 = (__ballot_sync(0xffffffffu, hv != 0ULL) == 0u);

        const int row = (bx - NBLK_BUILD) * 256 + tid;
        int t0, t1;
        if (is64) {
            longlong2 te = reinterpret_cast<const longlong2*>(TEp)[row];
            t0 = (int)te.x; t1 = (int)te.y;
        } else {
            int2 te = reinterpret_cast<const int2*>(TEp)[row];
            t0 = te.x; t1 = te.y;
        }
        int day = t0 % NDAY; day += (day >> 31) & NDAY;
        int tod = t1 % NT;   tod += (tod >> 31) & NT;
        int c   = day * NT + tod;
        int slot = atomicAdd(&g_cnt[c], 1);
        if (slot < CAP) g_rowlist[c * CAP + slot] = row;
        return;
    }

    // ---- build block ----
    const int mb = bx >> 3;        // m-block 0..125
    const int ks = bx & 7;         // k-eighth 0..7
    const int c0 = mb * MTILE;
    const int k0 = ks * KQ;

    __shared__ __align__(16) float h_sh[MTILE][KQ];   // 16 x 32 x 4B = 2 KB

    // Phase 1: h slice. 16*32 = 512 values, 256 threads.
    #pragma unroll
    for (int it = 0; it < (MTILE * KQ) / 256; it++) {
        int idx = it * 256 + tid;
        int m   = idx >> 5;            // /KQ
        int kk  = idx & (KQ - 1);
        int c   = c0 + m;
        int day = c / NT;
        int tod = c - day * NT;
        int k   = k0 + kk;
        float v = W1[day * D + k] + W1[(NDAY + tod) * D + k] + b1[k];
        h_sh[m][kk] = fmaxf(v, 0.0f);
    }
    __syncthreads();

    // Phase 2: partial GEMM. Thread -> columns (e, e+128), combos m0..m0+7.
    const int e    = tid & 127;
    const int half = tid >> 7;
    const int m0   = half * MPT;

    float acc0[MPT];   // column e
    float acc1[MPT];   // column e + 128
    const float i0 = (ks == 0) ? b2[e]       : 0.0f;
    const float i1 = (ks == 0) ? b2[e + 128] : 0.0f;
    #pragma unroll
    for (int m = 0; m < MPT; m++) { acc0[m] = i0; acc1[m] = i1; }

    #pragma unroll
    for (int kk = 0; kk < KQ; kk += 4) {
        const float* w = W2 + (size_t)(k0 + kk) * D + e;
        float wa0 = w[0 * D],       wa1 = w[1 * D];
        float wa2 = w[2 * D],       wa3 = w[3 * D];
        float wb0 = w[0 * D + 128], wb1 = w[1 * D + 128];
        float wb2 = w[2 * D + 128], wb3 = w[3 * D + 128];
        #pragma unroll
        for (int m = 0; m < MPT; m++) {
            float4 h4 = *reinterpret_cast<const float4*>(&h_sh[m0 + m][kk]);
            acc0[m] = fmaf(h4.x, wa0, acc0[m]);
            acc0[m] = fmaf(h4.y, wa1, acc0[m]);
            acc0[m] = fmaf(h4.z, wa2, acc0[m]);
            acc0[m] = fmaf(h4.w, wa3, acc0[m]);
            acc1[m] = fmaf(h4.x, wb0, acc1[m]);
            acc1[m] = fmaf(h4.y, wb1, acc1[m]);
            acc1[m] = fmaf(h4.z, wb2, acc1[m]);
            acc1[m] = fmaf(h4.w, wb3, acc1[m]);
        }
    }

    float* __restrict__ part = g_part[ks];
    #pragma unroll
    for (int m = 0; m < MPT; m++) {
        part[(size_t)(c0 + m0 + m) * D + e]       = acc0[m];
        part[(size_t)(c0 + m0 + m) * D + e + 128] = acc1[m];
    }
}

// -------------------------------------------------------------------------
// Kernel 2: block per combo (2016 blocks x 256 threads).
// Key change vs R9: the bucket's row ids are staged into SHARED with one
// coalesced load (256 threads cover CAP=256), so the store loop's address
// source is a 29-cycle LDS instead of a serial ~250-cycle L2 load chain.
// Threads 0..63 sum the 8 partials into smem; the 8 warps then stream the
// 1 KB row to bucket entries i = warp, warp+8, ... with __stcs STG.128.
// Tail: re-zero g_cnt[c] for the next graph replay.
// -------------------------------------------------------------------------
__global__ void __launch_bounds__(256) write_out(float* __restrict__ out)
{
    __shared__ __align__(16) float row_sh[D];
    __shared__ int   list_sh[CAP];

    const int c    = blockIdx.x;
    const int tid  = threadIdx.x;
    const int lane = tid & 31;
    const int warp = tid >> 5;

    int cnt = g_cnt[c];
    if (cnt > CAP) cnt = CAP;

    // Stage row ids: one coalesced pass (CAP == blockDim.x).
    if (tid < cnt) list_sh[tid] = g_rowlist[c * CAP + tid];

    // Reduce the 8 partials for this combo's row into shared.
    if (tid < 64) {
        const size_t base = (size_t)c * (D / 4) + tid;
        float4 s = reinterpret_cast<const float4*>(g_part[0])[base];
        #pragma unroll
        for (int p = 1; p < KSPLIT; p++) {
            float4 v = reinterpret_cast<const float4*>(g_part[p])[base];
            s.x += v.x; s.y += v.y; s.z += v.z; s.w += v.w;
        }
        reinterpret_cast<float4*>(row_sh)[tid] = s;
    }
    __syncthreads();

    // Each lane keeps its 2 float4 of the row in registers.
    float4 v0 = reinterpret_cast<const float4*>(row_sh)[lane];
    float4 v1 = reinterpret_cast<const float4*>(row_sh)[lane + 32];

    // Pure-STG streaming loop: ids come from shared (no global chain).
    for (int i = warp; i < cnt; i += 8) {
        int r = list_sh[i];
        float4* __restrict__ dst = reinterpret_cast<float4*>(out + (size_t)r * D);
        __stcs(dst + lane,      v0);
        __stcs(dst + lane + 32, v1);
    }

    // Reset the bucket counter for the next graph replay (g_cnt[c] was read
    // by all threads? no — read before the barrier by thread path above is
    // per-thread local; the barrier orders the reset after staging).
    __syncthreads();
    if (tid == 0) g_cnt[c] = 0;
}

// -------------------------------------------------------------------------
// Launch. Inputs resolved by element count:
//   TE = d_in[0]; W1: 295*256 = 75520; W2: 256*256 = 65536; b1/b2: 256 each.
// -------------------------------------------------------------------------
extern "C" void kernel_launch(void* const* d_in, const int* in_sizes, int n_in,
                              void* d_out, int out_size)
{
    const void* TE = d_in[0];
    const float* W1 = nullptr;
    const float* b1 = nullptr;
    const float* W2 = nullptr;
    const float* b2 = nullptr;

    for (int j = 1; j < n_in; j++) {
        int sz = in_sizes[j];
        if (sz == (NDAY + NT) * D) {
            W1 = (const float*)d_in[j];
        } else if (sz == D * D) {
            W2 = (const float*)d_in[j];
        } else if (sz == D) {
            if (!b1) b1 = (const float*)d_in[j];
            else     b2 = (const float*)d_in[j];
        }
    }
    if (!W1 || !b1 || !W2 || !b2) return;

    float* out = (float*)d_out;

    build_and_scatter<<<NBLK_BUILD + NBLK_SCAT, 256>>>(W1, b1, W2, b2, TE);
    write_out<<<NC, 256>>>(out);
}